// round 5
// baseline (speedup 1.0000x reference)
#include <cuda_runtime.h>
#include <math_constants.h>

// Problem constants
#define BB   16
#define DD   1024
#define TT   4096
#define CDIM 8
#define CSZ  1024

#define NTHREADS 256
#define TV   2
#define TILE 128                   // t per block
#define NQ   4                     // quarters, mapped to lane groups
#define DQ   (DD / NQ)             // 256
#define CQ   (CSZ / NQ)            // 256
#define TILES_PER_B (TT / TILE)    // 32
#define GRID (BB * TILES_PER_B)    // 512

// Padded pair-interleaved codebook: quarter stride 2052 floats (16B stagger
// per quarter -> conflict-free 4-address LDS.128 within a warp).
#define CBQ_STRIDE 2052
#define CB2_FLOATS (NQ * CBQ_STRIDE)   // 8208

// Output layout (concatenated float32):
// out [B,D,T], commitment_loss [B], codebook_loss [B], indices [B,T], z_e [B,CD,T]
#define OFF_CL  (BB * DD * TT)
#define OFF_CB  (OFF_CL + BB)
#define OFF_IDX (OFF_CB + BB)
#define OFF_ZE  (OFF_IDX + BB * TT)

// Device-global scratch
__device__ float g_winT[DD * CDIM];      // in-proj weight transposed [d][k]
__device__ float g_wout[DD * CDIM];      // out-proj weight [d][k] (natural)
__device__ float g_cbn2[CB2_FLOATS];     // normalized codebook, pair-interleaved+padded
__device__ float g_losspart[GRID * 8];   // per (block, warp)

// ---------------- f32x2 packed helpers ----------------
typedef unsigned long long u64;

__device__ __forceinline__ u64 pk(float lo, float hi) {
    u64 r; asm("mov.b64 %0, {%1, %2};" : "=l"(r) : "f"(lo), "f"(hi)); return r;
}
__device__ __forceinline__ void upk(float& lo, float& hi, u64 v) {
    asm("mov.b64 {%0, %1}, %2;" : "=f"(lo), "=f"(hi) : "l"(v));
}
__device__ __forceinline__ u64 f2(u64 a, u64 b, u64 c) {
    u64 d; asm("fma.rn.f32x2 %0, %1, %2, %3;" : "=l"(d) : "l"(a), "l"(b), "l"(c)); return d;
}
__device__ __forceinline__ u64 a2(u64 a, u64 b) {
    u64 d; asm("add.rn.f32x2 %0, %1, %2;" : "=l"(d) : "l"(a), "l"(b)); return d;
}

// ---------------------------------------------------------------------------
// Prep: blocks 0..7 -> weight-norm in_proj row o (norm over D), transpose.
//       blocks 8..11 -> weight-norm out_proj rows + normalized codebook
//                       (pair-interleaved, quarter-padded).
// ---------------------------------------------------------------------------
__global__ void vq_prep(const float* __restrict__ ipv, const float* __restrict__ ipg,
                        const float* __restrict__ opv, const float* __restrict__ opg,
                        const float* __restrict__ cb) {
    if (blockIdx.x < CDIM) {
        int o = blockIdx.x;
        __shared__ float red[256];
        float s = 0.f;
        for (int d = threadIdx.x; d < DD; d += blockDim.x) {
            float x = ipv[o * DD + d];
            s = fmaf(x, x, s);
        }
        red[threadIdx.x] = s;
        __syncthreads();
        for (int off = 128; off > 0; off >>= 1) {
            if (threadIdx.x < off) red[threadIdx.x] += red[threadIdx.x + off];
            __syncthreads();
        }
        float scale = ipg[o] / sqrtf(red[0]);
        for (int d = threadIdx.x; d < DD; d += blockDim.x)
            g_winT[d * CDIM + o] = ipv[o * DD + d] * scale;
    } else {
        int i = (blockIdx.x - CDIM) * 256 + threadIdx.x;
        if (i < DD) {
            float vv[CDIM];
            float s = 0.f;
#pragma unroll
            for (int c = 0; c < CDIM; c++) { vv[c] = opv[i * CDIM + c]; s = fmaf(vv[c], vv[c], s); }
            float sc = opg[i] / sqrtf(s);
#pragma unroll
            for (int c = 0; c < CDIM; c++) g_wout[i * CDIM + c] = vv[c] * sc;
        }
        if (i < CSZ) {
            float vv[CDIM];
            float s = 0.f;
#pragma unroll
            for (int k = 0; k < CDIM; k++) { vv[k] = cb[i * CDIM + k]; s = fmaf(vv[k], vv[k], s); }
            float inv = 1.f / fmaxf(sqrtf(s), 1e-12f);
            int q = i >> 8, cc = i & (CQ - 1);
            float* dst = g_cbn2 + q * CBQ_STRIDE + (cc >> 1) * 16 + (cc & 1);
#pragma unroll
            for (int k = 0; k < CDIM; k++) dst[k * 2] = vv[k] * inv;
        }
    }
}

// ---------------------------------------------------------------------------
// Main kernel. 256 threads; within each warp, lane groups of 8 are quarters
// (q = lid>>3). Each slot (wid*8 + lid&7) owns 2 adjacent t-columns.
// Quarters split d-space (P1, P3) and code-space (P2); ALL combines are
// intra-warp shfl butterflies -> no block syncs after codebook staging.
// winT / wout / bias are uniform LDG (L1/L2 resident); z via __ldcs,
// outputs via __stcs (evict-first, protect weight tables in cache).
// ---------------------------------------------------------------------------
__global__ void __launch_bounds__(NTHREADS, 4)
vq_main(const float* __restrict__ z,
        const float* __restrict__ in_b,
        const float* __restrict__ out_b,
        const float* __restrict__ cb,
        float* __restrict__ out) {
    extern __shared__ __align__(16) float s_cb[];   // 32.8 KB codebook

    const int tid  = threadIdx.x;
    const int wid  = tid >> 5;
    const int lid  = tid & 31;
    const int q    = lid >> 3;             // quarter 0..3
    const int slot = wid * 8 + (lid & 7);  // 0..63
    const int b    = blockIdx.x >> 5;
    const int tile = blockIdx.x & (TILES_PER_B - 1);
    const int t0   = tile * TILE + slot * TV;

    // ---- stage codebook (only block-wide sync in the kernel) ----
    {
        const float4* src = (const float4*)g_cbn2;
        float4* dst = (float4*)s_cb;
        for (int i = tid; i < CB2_FLOATS / 4; i += NTHREADS) dst[i] = src[i];
    }
    __syncthreads();

    // ---- phase 1: partial z_e over this quarter's 256 d's, 2 columns ----
    u64 aA[4] = {0, 0, 0, 0};
    u64 aB[4] = {0, 0, 0, 0};
    {
        const float* zp = z + (size_t)b * (DD * TT) + (size_t)(q * DQ) * TT + t0;
        const ulonglong2* wp = (const ulonglong2*)(g_winT + q * DQ * CDIM);
#pragma unroll 4
        for (int d = 0; d < DQ; d++) {
            float2 zv = __ldcs((const float2*)(zp + (size_t)d * TT));
            ulonglong2 w01 = __ldg(wp + 2 * d);
            ulonglong2 w23 = __ldg(wp + 2 * d + 1);
            u64 za = pk(zv.x, zv.x);
            u64 zb = pk(zv.y, zv.y);
            aA[0] = f2(w01.x, za, aA[0]);  aB[0] = f2(w01.x, zb, aB[0]);
            aA[1] = f2(w01.y, za, aA[1]);  aB[1] = f2(w01.y, zb, aB[1]);
            aA[2] = f2(w23.x, za, aA[2]);  aB[2] = f2(w23.x, zb, aB[2]);
            aA[3] = f2(w23.y, za, aA[3]);  aB[3] = f2(w23.y, zb, aB[3]);
        }
    }
    // combine quarters via intra-warp butterfly (lanes differ in bits 3,4)
#pragma unroll
    for (int j = 0; j < 4; j++) {
        aA[j] = a2(aA[j], __shfl_xor_sync(0xffffffffu, aA[j], 8));
        aB[j] = a2(aB[j], __shfl_xor_sync(0xffffffffu, aB[j], 8));
        aA[j] = a2(aA[j], __shfl_xor_sync(0xffffffffu, aA[j], 16));
        aB[j] = a2(aB[j], __shfl_xor_sync(0xffffffffu, aB[j], 16));
        float2 bj = __ldg((const float2*)in_b + j);
        u64 bp = pk(bj.x, bj.y);
        aA[j] = a2(aA[j], bp);
        aB[j] = a2(aB[j], bp);
    }

    // write z_e [B, CD, T] (quarter 0 lanes only)
    if (q == 0) {
        float* zeo = out + OFF_ZE + (size_t)b * (CDIM * TT) + t0;
#pragma unroll
        for (int j = 0; j < 4; j++) {
            float alo, ahi, blo, bhi;
            upk(alo, ahi, aA[j]);
            upk(blo, bhi, aB[j]);
            __stcs((float2*)(zeo + (size_t)(2 * j) * TT),     make_float2(alo, blo));
            __stcs((float2*)(zeo + (size_t)(2 * j + 1) * TT), make_float2(ahi, bhi));
        }
    }

    // duplicate-pack ze for the code-pair dot products
    u64 zdA[CDIM], zdB[CDIM];
#pragma unroll
    for (int j = 0; j < 4; j++) {
        float alo, ahi, blo, bhi;
        upk(alo, ahi, aA[j]);
        upk(blo, bhi, aB[j]);
        zdA[2 * j]     = pk(alo, alo);
        zdA[2 * j + 1] = pk(ahi, ahi);
        zdB[2 * j]     = pk(blo, blo);
        zdB[2 * j + 1] = pk(bhi, bhi);
    }

    // ---- phase 2: argmax over this quarter's 256 codes (2 codes/pass) ----
    float bestA = -CUDART_INF_F, bestB = -CUDART_INF_F;
    int biA = 0, biB = 0;
    {
        const float* cbase = s_cb + q * CBQ_STRIDE;
#pragma unroll 2
        for (int p = 0; p < CQ / 2; p++) {
            const ulonglong2* r = (const ulonglong2*)(cbase + p * 16);
            ulonglong2 r0 = r[0], r1 = r[1], r2 = r[2], r3 = r[3];
            u64 dA = 0, dB = 0;
            dA = f2(r0.x, zdA[0], dA);  dB = f2(r0.x, zdB[0], dB);
            dA = f2(r0.y, zdA[1], dA);  dB = f2(r0.y, zdB[1], dB);
            dA = f2(r1.x, zdA[2], dA);  dB = f2(r1.x, zdB[2], dB);
            dA = f2(r1.y, zdA[3], dA);  dB = f2(r1.y, zdB[3], dB);
            dA = f2(r2.x, zdA[4], dA);  dB = f2(r2.x, zdB[4], dB);
            dA = f2(r2.y, zdA[5], dA);  dB = f2(r2.y, zdB[5], dB);
            dA = f2(r3.x, zdA[6], dA);  dB = f2(r3.x, zdB[6], dB);
            dA = f2(r3.y, zdA[7], dA);  dB = f2(r3.y, zdB[7], dB);
            float e0, e1, f0, f1;
            upk(e0, e1, dA);
            upk(f0, f1, dB);
            int c0 = q * CQ + 2 * p;
            if (e0 > bestA) { bestA = e0; biA = c0; }     // strict >: first max wins
            if (e1 > bestA) { bestA = e1; biA = c0 + 1; }
            if (f0 > bestB) { bestB = f0; biB = c0; }
            if (f1 > bestB) { bestB = f1; biB = c0 + 1; }
        }
    }
    // combine argmax across quarters (min-index on exact ties = first max)
#pragma unroll
    for (int m = 8; m <= 16; m <<= 1) {
        float ovA = __shfl_xor_sync(0xffffffffu, bestA, m);
        int   oiA = __shfl_xor_sync(0xffffffffu, biA, m);
        if (ovA > bestA || (ovA == bestA && oiA < biA)) { bestA = ovA; biA = oiA; }
        float ovB = __shfl_xor_sync(0xffffffffu, bestB, m);
        int   oiB = __shfl_xor_sync(0xffffffffu, biB, m);
        if (ovB > bestB || (ovB == bestB && oiB < biB)) { bestB = ovB; biB = oiB; }
    }
    if (q == 0)
        __stcs((float2*)(out + OFF_IDX + (size_t)b * TT + t0),
               make_float2((float)biA, (float)biB));

    // gather raw codebook rows (L1/L2 resident)
    const float4* cb4 = (const float4*)cb;
    float4 qa0 = __ldg(cb4 + 2 * biA);
    float4 qa1 = __ldg(cb4 + 2 * biA + 1);
    float4 qb0 = __ldg(cb4 + 2 * biB);
    float4 qb1 = __ldg(cb4 + 2 * biB + 1);

    // ---- loss (each column duplicated 4x across quarter lanes -> x0.25 later)
    {
        float zqa[CDIM] = {qa0.x, qa0.y, qa0.z, qa0.w, qa1.x, qa1.y, qa1.z, qa1.w};
        float zqb[CDIM] = {qb0.x, qb0.y, qb0.z, qb0.w, qb1.x, qb1.y, qb1.z, qb1.w};
        float ls = 0.f;
#pragma unroll
        for (int j = 0; j < 4; j++) {
            float alo, ahi, blo, bhi;
            upk(alo, ahi, aA[j]);
            upk(blo, bhi, aB[j]);
            float d0 = alo - zqa[2 * j], d1 = ahi - zqa[2 * j + 1];
            float d2 = blo - zqb[2 * j], d3 = bhi - zqb[2 * j + 1];
            ls = fmaf(d0, d0, ls);
            ls = fmaf(d1, d1, ls);
            ls = fmaf(d2, d2, ls);
            ls = fmaf(d3, d3, ls);
        }
#pragma unroll
        for (int m = 16; m > 0; m >>= 1)
            ls += __shfl_xor_sync(0xffffffffu, ls, m);
        if (lid == 0) g_losspart[blockIdx.x * 8 + wid] = ls;
    }

    // ---- phase 3: out rows for this quarter's 256 d's, both columns ----
    {
        u64 zqA[4] = { pk(qa0.x, qa0.y), pk(qa0.z, qa0.w), pk(qa1.x, qa1.y), pk(qa1.z, qa1.w) };
        u64 zqB[4] = { pk(qb0.x, qb0.y), pk(qb0.z, qb0.w), pk(qb1.x, qb1.y), pk(qb1.z, qb1.w) };
        const ulonglong2* wp = (const ulonglong2*)(g_wout + q * DQ * CDIM);
        const float* bp = out_b + q * DQ;
        float* op = out + (size_t)b * (DD * TT) + (size_t)(q * DQ) * TT + t0;
#pragma unroll 4
        for (int d = 0; d < DQ; d++) {
            ulonglong2 w01 = __ldg(wp + 2 * d);
            ulonglong2 w23 = __ldg(wp + 2 * d + 1);
            float bd = __ldg(bp + d);
            u64 acA = 0, acB = 0;
            acA = f2(w01.x, zqA[0], acA);  acB = f2(w01.x, zqB[0], acB);
            acA = f2(w01.y, zqA[1], acA);  acB = f2(w01.y, zqB[1], acB);
            acA = f2(w23.x, zqA[2], acA);  acB = f2(w23.x, zqB[2], acB);
            acA = f2(w23.y, zqA[3], acA);  acB = f2(w23.y, zqB[3], acB);
            float la, ha, lb, hb;
            upk(la, ha, acA);
            upk(lb, hb, acB);
            __stcs((float2*)(op + (size_t)d * TT),
                   make_float2(la + ha + bd, lb + hb + bd));
        }
    }
}

// ---------------------------------------------------------------------------
// Finish: deterministic loss reduction. Warp w handles batch w: 256 partials
// (32 blocks x 8 warps), each column counted 4x -> scale by 0.25/(CD*T).
// ---------------------------------------------------------------------------
__global__ void vq_finish(float* __restrict__ out) {
    int w = threadIdx.x >> 5;
    int l = threadIdx.x & 31;
    if (w < BB) {
        const float* p = g_losspart + w * 256;
        float s = 0.f;
#pragma unroll
        for (int k = 0; k < 8; k++) s += p[l + 32 * k];
#pragma unroll
        for (int m = 16; m > 0; m >>= 1)
            s += __shfl_xor_sync(0xffffffffu, s, m);
        if (l == 0) {
            s *= 0.25f * (1.0f / (float)(CDIM * TT));
            out[OFF_CL + w] = s;
            out[OFF_CB + w] = s;
        }
    }
}

extern "C" void kernel_launch(void* const* d_in, const int* in_sizes, int n_in,
                              void* d_out, int out_size) {
    const float* z   = (const float*)d_in[0];
    const float* ipv = (const float*)d_in[1];
    const float* ipg = (const float*)d_in[2];
    const float* ipb = (const float*)d_in[3];
    const float* opv = (const float*)d_in[4];
    const float* opg = (const float*)d_in[5];
    const float* opb = (const float*)d_in[6];
    const float* cb  = (const float*)d_in[7];
    float* out = (float*)d_out;

    const int smem_bytes = CB2_FLOATS * sizeof(float);   // ~32.8 KB
    cudaFuncSetAttribute(vq_main, cudaFuncAttributeMaxDynamicSharedMemorySize, smem_bytes);

    vq_prep<<<CDIM + 4, 256>>>(ipv, ipg, opv, opg, cb);
    vq_main<<<GRID, NTHREADS, smem_bytes>>>(z, ipb, opb, cb, out);
    vq_finish<<<1, 512>>>(out);
}

// round 6
// speedup vs baseline: 1.2596x; 1.2596x over previous
#include <cuda_runtime.h>
#include <math_constants.h>

// Problem constants
#define BB   16
#define DD   1024
#define TT   4096
#define CDIM 8
#define CSZ  1024

#define NTHREADS 256
#define NQ   4                     // quarters: q = tid>>6 (warp pairs -> uniform)
#define SLOTS 64                   // thread slots per quarter
#define TV   2                     // t-columns per thread
#define TILE (SLOTS * TV)          // 128 t per block
#define DQ   (DD / NQ)             // 256
#define CQ   (CSZ / NQ)            // 256
#define TILES_PER_B (TT / TILE)    // 32
#define GRID (BB * TILES_PER_B)    // 512

// Output layout (concatenated float32):
// out [B,D,T], commitment_loss [B], codebook_loss [B], indices [B,T], z_e [B,CD,T]
#define OFF_CL  (BB * DD * TT)
#define OFF_CB  (OFF_CL + BB)
#define OFF_IDX (OFF_CB + BB)
#define OFF_ZE  (OFF_IDX + BB * TT)

// Device-global scratch (prep output) + constant weight banks (64KB total)
__device__ float g_winT[DD * CDIM];   // in-proj weight transposed [d][k]
__device__ float g_wout[DD * CDIM];   // out-proj weight [d][k]
__device__ float g_cbn[CSZ * CDIM];   // normalized codebook [c][k]
__device__ float g_losspart[GRID];

__constant__ float c_winT[DD * CDIM]; // 32 KB
__constant__ float c_wout[DD * CDIM]; // 32 KB

// ---------------- f32x2 packed helpers ----------------
typedef unsigned long long u64;

__device__ __forceinline__ u64 pk(float lo, float hi) {
    u64 r; asm("mov.b64 %0, {%1, %2};" : "=l"(r) : "f"(lo), "f"(hi)); return r;
}
__device__ __forceinline__ void upk(float& lo, float& hi, u64 v) {
    asm("mov.b64 {%0, %1}, %2;" : "=f"(lo), "=f"(hi) : "l"(v));
}
__device__ __forceinline__ u64 f2(u64 a, u64 b, u64 c) {
    u64 d; asm("fma.rn.f32x2 %0, %1, %2, %3;" : "=l"(d) : "l"(a), "l"(b), "l"(c)); return d;
}
__device__ __forceinline__ u64 a2(u64 a, u64 b) {
    u64 d; asm("add.rn.f32x2 %0, %1, %2;" : "=l"(d) : "l"(a), "l"(b)); return d;
}

// ---------------------------------------------------------------------------
// Prep: blocks 0..7 -> weight-norm in_proj row o (norm over D), transpose.
//       blocks 8..11 -> weight-norm out_proj rows + l2-normalized codebook.
// ---------------------------------------------------------------------------
__global__ void vq_prep(const float* __restrict__ ipv, const float* __restrict__ ipg,
                        const float* __restrict__ opv, const float* __restrict__ opg,
                        const float* __restrict__ cb) {
    if (blockIdx.x < CDIM) {
        int o = blockIdx.x;
        __shared__ float red[256];
        float s = 0.f;
        for (int d = threadIdx.x; d < DD; d += blockDim.x) {
            float x = ipv[o * DD + d];
            s = fmaf(x, x, s);
        }
        red[threadIdx.x] = s;
        __syncthreads();
        for (int off = 128; off > 0; off >>= 1) {
            if (threadIdx.x < off) red[threadIdx.x] += red[threadIdx.x + off];
            __syncthreads();
        }
        float scale = ipg[o] / sqrtf(red[0]);
        for (int d = threadIdx.x; d < DD; d += blockDim.x)
            g_winT[d * CDIM + o] = ipv[o * DD + d] * scale;
    } else {
        int i = (blockIdx.x - CDIM) * 256 + threadIdx.x;
        if (i < DD) {
            float vv[CDIM];
            float s = 0.f;
#pragma unroll
            for (int c = 0; c < CDIM; c++) { vv[c] = opv[i * CDIM + c]; s = fmaf(vv[c], vv[c], s); }
            float sc = opg[i] / sqrtf(s);
#pragma unroll
            for (int c = 0; c < CDIM; c++) g_wout[i * CDIM + c] = vv[c] * sc;
        }
        if (i < CSZ) {
            float vv[CDIM];
            float s = 0.f;
#pragma unroll
            for (int k = 0; k < CDIM; k++) { vv[k] = cb[i * CDIM + k]; s = fmaf(vv[k], vv[k], s); }
            float inv = 1.f / fmaxf(sqrtf(s), 1e-12f);
#pragma unroll
            for (int k = 0; k < CDIM; k++) g_cbn[i * CDIM + k] = vv[k] * inv;
        }
    }
}

// ---------------------------------------------------------------------------
// Main kernel (R3 structure). 256 threads = 4 quarters x 64 slots, TV=2.
// Quarter = warp pair -> ALL weight accesses warp-uniform -> constant bank
// uniform loads. Codebook staged ONCE in smem; phase2 -> phase3 is sync-free
// (weights in const, zq thread-local) so warps/blocks desynchronize and
// reads/compute/writes overlap chip-wide.
// ---------------------------------------------------------------------------
__global__ void __launch_bounds__(NTHREADS, 4)
vq_main(const float* __restrict__ z,
        const float* __restrict__ in_b,
        const float* __restrict__ out_b,
        const float* __restrict__ cb,
        float* __restrict__ out) {
    extern __shared__ __align__(16) char smem[];
    float* s_cb = (float*)smem;                    // 32 KB: normalized codebook [c][k]
    u64*   s_ex = (u64*)(smem + 32768);            // 16 KB exchange:
    float* s_best = (float*)s_ex;                  //   [NQ][TILE] floats (2 KB)
    int*   s_bi   = (int*)s_ex + NQ * TILE;        //   [NQ][TILE] ints   (2 KB)
    float* s_red  = (float*)(smem + 32768 + 16384);//   8 floats

    const int tid  = threadIdx.x;
    const int q    = tid >> 6;          // quarter 0..3 (uniform per warp)
    const int slot = tid & (SLOTS - 1); // 0..63
    const int blk  = blockIdx.x;
    const int b    = blk / TILES_PER_B;
    const int t0   = (blk % TILES_PER_B) * TILE + slot * TV;

    // ---- stage codebook once (the only table in smem) ----
    {
        const float4* src = (const float4*)g_cbn;
        float4* dst = (float4*)s_cb;
        for (int i = tid; i < CSZ * CDIM / 4; i += NTHREADS) dst[i] = src[i];
    }
    __syncthreads();

    // ---- phase 1: partial z_e over this quarter's 256 d's, 2 columns ----
    u64 aA[4] = {0, 0, 0, 0};
    u64 aB[4] = {0, 0, 0, 0};
    {
        const float* zp = z + (size_t)b * (DD * TT) + (size_t)(q * DQ) * TT + t0;
        const ulonglong2* wp = (const ulonglong2*)c_winT + 2 * q * DQ;
#pragma unroll 4
        for (int d = 0; d < DQ; d++) {
            float2 zv = __ldcs((const float2*)(zp + (size_t)d * TT));
            ulonglong2 w01 = wp[2 * d];        // warp-uniform const load
            ulonglong2 w23 = wp[2 * d + 1];
            u64 za = pk(zv.x, zv.x);
            u64 zb = pk(zv.y, zv.y);
            aA[0] = f2(w01.x, za, aA[0]);  aB[0] = f2(w01.x, zb, aB[0]);
            aA[1] = f2(w01.y, za, aA[1]);  aB[1] = f2(w01.y, zb, aB[1]);
            aA[2] = f2(w23.x, za, aA[2]);  aB[2] = f2(w23.x, zb, aB[2]);
            aA[3] = f2(w23.y, za, aA[3]);  aB[3] = f2(w23.y, zb, aB[3]);
        }
    }
    // publish partials: layout [j][col][q][slot]
#pragma unroll
    for (int j = 0; j < 4; j++) {
        s_ex[((j * 2 + 0) * NQ + q) * SLOTS + slot] = aA[j];
        s_ex[((j * 2 + 1) * NQ + q) * SLOTS + slot] = aB[j];
    }
    __syncthreads();

    // combine quarters (ascending) + bias; all threads get full ze (k-pair packed)
    u64 zeA[4], zeB[4];
    {
        const float2* bb = (const float2*)in_b;
#pragma unroll
        for (int j = 0; j < 4; j++) {
            float2 bj = __ldg(bb + j);
            u64 bp = pk(bj.x, bj.y);
            u64 sa = s_ex[((j * 2 + 0) * NQ + 0) * SLOTS + slot];
            u64 sb = s_ex[((j * 2 + 1) * NQ + 0) * SLOTS + slot];
#pragma unroll
            for (int qq = 1; qq < NQ; qq++) {
                sa = a2(sa, s_ex[((j * 2 + 0) * NQ + qq) * SLOTS + slot]);
                sb = a2(sb, s_ex[((j * 2 + 1) * NQ + qq) * SLOTS + slot]);
            }
            zeA[j] = a2(sa, bp);
            zeB[j] = a2(sb, bp);
        }
    }

    // write z_e [B, CD, T] (quarter 0 only; STG.64 on t-pairs)
    if (q == 0) {
        float* zeo = out + OFF_ZE + (size_t)b * (CDIM * TT) + t0;
#pragma unroll
        for (int j = 0; j < 4; j++) {
            float a0, a1, b0, b1;
            upk(a0, a1, zeA[j]);
            upk(b0, b1, zeB[j]);
            __stcs((float2*)(zeo + (size_t)(2 * j) * TT),     make_float2(a0, b0));
            __stcs((float2*)(zeo + (size_t)(2 * j + 1) * TT), make_float2(a1, b1));
        }
    }
    __syncthreads();   // partials exchange complete; s_ex reused for argmax

    // ---- phase 2: argmax over this quarter's 256 codes, both columns ----
    float bestA = -CUDART_INF_F, bestB = -CUDART_INF_F;
    int biA = 0, biB = 0;
    {
        const float* cbase = s_cb + q * CQ * CDIM;
#pragma unroll 2
        for (int cc = 0; cc < CQ; cc++) {
            const ulonglong2* r = (const ulonglong2*)(cbase + cc * CDIM);
            ulonglong2 c01 = r[0];   // warp-uniform LDS (broadcast)
            ulonglong2 c23 = r[1];
            u64 da = 0, db = 0;
            da = f2(c01.x, zeA[0], da);  db = f2(c01.x, zeB[0], db);
            da = f2(c01.y, zeA[1], da);  db = f2(c01.y, zeB[1], db);
            da = f2(c23.x, zeA[2], da);  db = f2(c23.x, zeB[2], db);
            da = f2(c23.y, zeA[3], da);  db = f2(c23.y, zeB[3], db);
            float la, ha, lb, hb;
            upk(la, ha, da);
            upk(lb, hb, db);
            float dotA = la + ha;
            float dotB = lb + hb;
            int c = q * CQ + cc;
            if (dotA > bestA) { bestA = dotA; biA = c; }   // strict >: first max wins
            if (dotB > bestB) { bestB = dotB; biB = c; }
        }
    }
    s_best[q * TILE + slot * 2]     = bestA;
    s_best[q * TILE + slot * 2 + 1] = bestB;
    s_bi[q * TILE + slot * 2]       = biA;
    s_bi[q * TILE + slot * 2 + 1]   = biB;
    __syncthreads();

    // combine argmax across quarters (ascending q keeps first-index semantics)
    int fbiA, fbiB;
    {
        float vA = s_best[slot * 2], vB = s_best[slot * 2 + 1];
        fbiA = s_bi[slot * 2];  fbiB = s_bi[slot * 2 + 1];
#pragma unroll
        for (int qq = 1; qq < NQ; qq++) {
            float wA = s_best[qq * TILE + slot * 2];
            float wB = s_best[qq * TILE + slot * 2 + 1];
            if (wA > vA) { vA = wA; fbiA = s_bi[qq * TILE + slot * 2]; }
            if (wB > vB) { vB = wB; fbiB = s_bi[qq * TILE + slot * 2 + 1]; }
        }
    }
    if (q == 0)
        __stcs((float2*)(out + OFF_IDX + (size_t)b * TT + t0),
               make_float2((float)fbiA, (float)fbiB));

    // gather raw codebook rows (L1/L2 resident)
    const float4* cb4 = (const float4*)cb;
    float4 qa0 = __ldg(cb4 + 2 * fbiA);
    float4 qa1 = __ldg(cb4 + 2 * fbiA + 1);
    float4 qb0 = __ldg(cb4 + 2 * fbiB);
    float4 qb1 = __ldg(cb4 + 2 * fbiB + 1);

    // loss scalar (all quarters duplicate -> x0.25 at the end); reduce AFTER P3
    float ls = 0.f;
    {
        float zqa[CDIM] = {qa0.x, qa0.y, qa0.z, qa0.w, qa1.x, qa1.y, qa1.z, qa1.w};
        float zqb[CDIM] = {qb0.x, qb0.y, qb0.z, qb0.w, qb1.x, qb1.y, qb1.z, qb1.w};
#pragma unroll
        for (int j = 0; j < 4; j++) {
            float a0, a1, b0, b1;
            upk(a0, a1, zeA[j]);
            upk(b0, b1, zeB[j]);
            float d0 = a0 - zqa[2 * j], d1 = a1 - zqa[2 * j + 1];
            float d2 = b0 - zqb[2 * j], d3 = b1 - zqb[2 * j + 1];
            ls = fmaf(d0, d0, ls);
            ls = fmaf(d1, d1, ls);
            ls = fmaf(d2, d2, ls);
            ls = fmaf(d3, d3, ls);
        }
    }

    // ---- phase 3 (NO sync before: const weights + local zq) ----
    {
        u64 zqA[4] = { pk(qa0.x, qa0.y), pk(qa0.z, qa0.w), pk(qa1.x, qa1.y), pk(qa1.z, qa1.w) };
        u64 zqB[4] = { pk(qb0.x, qb0.y), pk(qb0.z, qb0.w), pk(qb1.x, qb1.y), pk(qb1.z, qb1.w) };
        const ulonglong2* wp = (const ulonglong2*)c_wout + 2 * q * DQ;
        const float* bp = out_b + q * DQ;
        float* op = out + (size_t)b * (DD * TT) + (size_t)(q * DQ) * TT + t0;
#pragma unroll 4
        for (int d = 0; d < DQ; d++) {
            ulonglong2 w01 = wp[2 * d];        // warp-uniform const load
            ulonglong2 w23 = wp[2 * d + 1];
            float bd = __ldg(bp + d);
            u64 acA = 0, acB = 0;
            acA = f2(w01.x, zqA[0], acA);  acB = f2(w01.x, zqB[0], acB);
            acA = f2(w01.y, zqA[1], acA);  acB = f2(w01.y, zqB[1], acB);
            acA = f2(w23.x, zqA[2], acA);  acB = f2(w23.x, zqB[2], acB);
            acA = f2(w23.y, zqA[3], acA);  acB = f2(w23.y, zqB[3], acB);
            float la, ha, lb, hb;
            upk(la, ha, acA);
            upk(lb, hb, acB);
            __stcs((float2*)(op + (size_t)d * TT),
                   make_float2(la + ha + bd, lb + hb + bd));
        }
    }

    // ---- block loss reduction (deterministic), after all heavy work ----
#pragma unroll
    for (int m = 16; m > 0; m >>= 1)
        ls += __shfl_xor_sync(0xffffffffu, ls, m);
    if ((tid & 31) == 0) s_red[tid >> 5] = ls;
    __syncthreads();
    if (tid == 0) {
        float tot = 0.f;
#pragma unroll
        for (int w = 0; w < NTHREADS / 32; w++) tot += s_red[w];
        g_losspart[blk] = tot * 0.25f;   // quarters quadruplicate each column
    }
}

// ---------------------------------------------------------------------------
// Finish: deterministic fixed-order loss reduction.
// ---------------------------------------------------------------------------
__global__ void vq_finish(float* __restrict__ out) {
    int b = threadIdx.x;
    if (b < BB) {
        float s = 0.f;
        for (int i = 0; i < TILES_PER_B; i++) s += g_losspart[b * TILES_PER_B + i];
        s *= (1.0f / (float)(CDIM * TT));
        out[OFF_CL + b] = s;
        out[OFF_CB + b] = s;
    }
}

extern "C" void kernel_launch(void* const* d_in, const int* in_sizes, int n_in,
                              void* d_out, int out_size) {
    const float* z   = (const float*)d_in[0];
    const float* ipv = (const float*)d_in[1];
    const float* ipg = (const float*)d_in[2];
    const float* ipb = (const float*)d_in[3];
    const float* opv = (const float*)d_in[4];
    const float* opg = (const float*)d_in[5];
    const float* opb = (const float*)d_in[6];
    const float* cb  = (const float*)d_in[7];
    float* out = (float*)d_out;

    const int smem_bytes = 32768 + 16384 + 64;  // cb + exchange + red
    cudaFuncSetAttribute(vq_main, cudaFuncAttributeMaxDynamicSharedMemorySize, smem_bytes);

    vq_prep<<<CDIM + 4, 256>>>(ipv, ipg, opv, opg, cb);

    // copy processed weights into the constant banks (graph-capturable D2D)
    void *p_winT = nullptr, *p_wout = nullptr;
    cudaGetSymbolAddress(&p_winT, g_winT);
    cudaGetSymbolAddress(&p_wout, g_wout);
    cudaMemcpyToSymbolAsync(c_winT, p_winT, DD * CDIM * sizeof(float), 0,
                            cudaMemcpyDeviceToDevice, 0);
    cudaMemcpyToSymbolAsync(c_wout, p_wout, DD * CDIM * sizeof(float), 0,
                            cudaMemcpyDeviceToDevice, 0);

    vq_main<<<GRID, NTHREADS, smem_bytes>>>(z, ipb, opb, cb, out);
    vq_finish<<<1, 32>>>(out);
}

// round 7
// speedup vs baseline: 1.3210x; 1.0487x over previous
#include <cuda_runtime.h>
#include <math_constants.h>

// Problem constants
#define BB   16
#define DD   1024
#define TT   4096
#define CDIM 8
#define CSZ  1024

#define NTHREADS 256
#define NG   8                     // groups (= warps): d-split / code-split
#define SLOTS 32                   // thread slots per group (one warp)
#define TV   2                     // t-columns per thread
#define TILE (SLOTS * TV)          // 64 t per block
#define DG   (DD / NG)             // 128 d per group
#define CG   (CSZ / NG)            // 128 codes per group
#define TILES_PER_B (TT / TILE)    // 64
#define GRID (BB * TILES_PER_B)    // 1024  (~1.7 waves at occ 4 -> phase mixing)

// Output layout (concatenated float32):
// out [B,D,T], commitment_loss [B], codebook_loss [B], indices [B,T], z_e [B,CD,T]
#define OFF_CL  (BB * DD * TT)
#define OFF_CB  (OFF_CL + BB)
#define OFF_IDX (OFF_CB + BB)
#define OFF_ZE  (OFF_IDX + BB * TT)

// Device-global scratch
__device__ float g_winT[DD * CDIM];   // in-proj weight transposed [d][k]
__device__ float g_wout[DD * CDIM];   // out-proj weight [d][k]
__device__ float g_cbn[CSZ * CDIM];   // normalized codebook [c][k]
__device__ float g_losspart[GRID];
__device__ unsigned int g_done;       // zero-init; self-resetting

// ---------------- f32x2 packed helpers ----------------
typedef unsigned long long u64;

__device__ __forceinline__ u64 pk(float lo, float hi) {
    u64 r; asm("mov.b64 %0, {%1, %2};" : "=l"(r) : "f"(lo), "f"(hi)); return r;
}
__device__ __forceinline__ void upk(float& lo, float& hi, u64 v) {
    asm("mov.b64 {%0, %1}, %2;" : "=f"(lo), "=f"(hi) : "l"(v));
}
__device__ __forceinline__ u64 f2(u64 a, u64 b, u64 c) {
    u64 d; asm("fma.rn.f32x2 %0, %1, %2, %3;" : "=l"(d) : "l"(a), "l"(b), "l"(c)); return d;
}
__device__ __forceinline__ u64 a2(u64 a, u64 b) {
    u64 d; asm("add.rn.f32x2 %0, %1, %2;" : "=l"(d) : "l"(a), "l"(b)); return d;
}

// ---------------------------------------------------------------------------
// Prep: blocks 0..7 -> weight-norm in_proj row o (norm over D), transpose.
//       blocks 8..11 -> weight-norm out_proj rows + l2-normalized codebook.
// ---------------------------------------------------------------------------
__global__ void vq_prep(const float* __restrict__ ipv, const float* __restrict__ ipg,
                        const float* __restrict__ opv, const float* __restrict__ opg,
                        const float* __restrict__ cb) {
    if (blockIdx.x < CDIM) {
        int o = blockIdx.x;
        __shared__ float red[256];
        float s = 0.f;
        for (int d = threadIdx.x; d < DD; d += blockDim.x) {
            float x = ipv[o * DD + d];
            s = fmaf(x, x, s);
        }
        red[threadIdx.x] = s;
        __syncthreads();
        for (int off = 128; off > 0; off >>= 1) {
            if (threadIdx.x < off) red[threadIdx.x] += red[threadIdx.x + off];
            __syncthreads();
        }
        float scale = ipg[o] / sqrtf(red[0]);
        for (int d = threadIdx.x; d < DD; d += blockDim.x)
            g_winT[d * CDIM + o] = ipv[o * DD + d] * scale;
    } else {
        int i = (blockIdx.x - CDIM) * 256 + threadIdx.x;
        if (i < DD) {
            float vv[CDIM];
            float s = 0.f;
#pragma unroll
            for (int c = 0; c < CDIM; c++) { vv[c] = opv[i * CDIM + c]; s = fmaf(vv[c], vv[c], s); }
            float sc = opg[i] / sqrtf(s);
#pragma unroll
            for (int c = 0; c < CDIM; c++) g_wout[i * CDIM + c] = vv[c] * sc;
        }
        if (i < CSZ) {
            float vv[CDIM];
            float s = 0.f;
#pragma unroll
            for (int k = 0; k < CDIM; k++) { vv[k] = cb[i * CDIM + k]; s = fmaf(vv[k], vv[k], s); }
            float inv = 1.f / fmaxf(sqrtf(s), 1e-12f);
#pragma unroll
            for (int k = 0; k < CDIM; k++) g_cbn[i * CDIM + k] = vv[k] * inv;
        }
    }
}

// ---------------------------------------------------------------------------
// Main kernel (R3 structure, half tile, 8 groups, fused finish).
// 256 threads = 8 groups (one warp each) x 32 slots, TV=2.
// Group = warp -> all table accesses are warp-uniform LDS broadcasts.
// 32KB smem buffer time-shared winT -> cbn -> wout; 16KB exchange.
// Grid = 1024 (~1.7 waves) so blocks naturally mix phases chip-wide.
// ---------------------------------------------------------------------------
__global__ void __launch_bounds__(NTHREADS, 4)
vq_main(const float* __restrict__ z,
        const float* __restrict__ in_b,
        const float* __restrict__ out_b,
        const float* __restrict__ cb,
        float* __restrict__ out) {
    extern __shared__ __align__(16) char smem[];
    float* s_w    = (float*)smem;                     // 32 KB: winT -> cbn -> wout
    u64*   s_ex   = (u64*)(smem + 32768);             // 16 KB exchange
    float* s_best = (float*)s_ex;                     //   [NG][TILE] floats (2 KB)
    int*   s_bi   = (int*)s_ex + NG * TILE;           //   [NG][TILE] ints   (2 KB)
    float* s_bias = (float*)(smem + 32768 + 16384);   // 4 KB out-proj bias
    float* s_red  = (float*)(smem + 32768 + 16384 + 4096); // 8 floats

    const int tid  = threadIdx.x;
    const int g    = tid >> 5;          // group 0..7 (= warp id, uniform)
    const int slot = tid & (SLOTS - 1); // 0..31
    const int blk  = blockIdx.x;
    const int b    = blk / TILES_PER_B;
    const int t0   = (blk % TILES_PER_B) * TILE + slot * TV;

    // ---- stage in-proj weight (transposed) ----
    {
        const float4* src = (const float4*)g_winT;
        float4* dst = (float4*)s_w;
        for (int i = tid; i < DD * CDIM / 4; i += NTHREADS) dst[i] = src[i];
    }
    __syncthreads();

    // ---- phase 1: partial z_e over this group's 128 d's, 2 columns ----
    u64 aA[4] = {0, 0, 0, 0};
    u64 aB[4] = {0, 0, 0, 0};
    {
        const float* zp = z + (size_t)b * (DD * TT) + (size_t)(g * DG) * TT + t0;
        const ulonglong2* wp = (const ulonglong2*)(s_w + g * DG * CDIM);
#pragma unroll 4
        for (int d = 0; d < DG; d++) {
            float2 zv = __ldcs((const float2*)(zp + (size_t)d * TT));
            ulonglong2 w01 = wp[2 * d];        // warp-uniform LDS broadcast
            ulonglong2 w23 = wp[2 * d + 1];
            u64 za = pk(zv.x, zv.x);
            u64 zb = pk(zv.y, zv.y);
            aA[0] = f2(w01.x, za, aA[0]);  aB[0] = f2(w01.x, zb, aB[0]);
            aA[1] = f2(w01.y, za, aA[1]);  aB[1] = f2(w01.y, zb, aB[1]);
            aA[2] = f2(w23.x, za, aA[2]);  aB[2] = f2(w23.x, zb, aB[2]);
            aA[3] = f2(w23.y, za, aA[3]);  aB[3] = f2(w23.y, zb, aB[3]);
        }
    }
    // publish partials: layout [j*2+col][g][slot]
#pragma unroll
    for (int j = 0; j < 4; j++) {
        s_ex[((j * 2 + 0) * NG + g) * SLOTS + slot] = aA[j];
        s_ex[((j * 2 + 1) * NG + g) * SLOTS + slot] = aB[j];
    }
    __syncthreads();

    // combine groups (ascending) + bias; all threads get full ze (k-pair packed)
    u64 zeA[4], zeB[4];
    {
        const float2* bb = (const float2*)in_b;
#pragma unroll
        for (int j = 0; j < 4; j++) {
            float2 bj = __ldg(bb + j);
            u64 bp = pk(bj.x, bj.y);
            u64 sa = s_ex[((j * 2 + 0) * NG + 0) * SLOTS + slot];
            u64 sb = s_ex[((j * 2 + 1) * NG + 0) * SLOTS + slot];
#pragma unroll
            for (int gg = 1; gg < NG; gg++) {
                sa = a2(sa, s_ex[((j * 2 + 0) * NG + gg) * SLOTS + slot]);
                sb = a2(sb, s_ex[((j * 2 + 1) * NG + gg) * SLOTS + slot]);
            }
            zeA[j] = a2(sa, bp);
            zeB[j] = a2(sb, bp);
        }
    }

    // write z_e [B, CD, T] (group 0 only; STG.64 on t-pairs)
    if (g == 0) {
        float* zeo = out + OFF_ZE + (size_t)b * (CDIM * TT) + t0;
#pragma unroll
        for (int j = 0; j < 4; j++) {
            float a0, a1, b0, b1;
            upk(a0, a1, zeA[j]);
            upk(b0, b1, zeB[j]);
            __stcs((float2*)(zeo + (size_t)(2 * j) * TT),     make_float2(a0, b0));
            __stcs((float2*)(zeo + (size_t)(2 * j + 1) * TT), make_float2(a1, b1));
        }
    }
    __syncthreads();   // partial exchange consumed; s_w refill next

    // ---- stage normalized codebook ----
    {
        const float4* src = (const float4*)g_cbn;
        float4* dst = (float4*)s_w;
        for (int i = tid; i < CSZ * CDIM / 4; i += NTHREADS) dst[i] = src[i];
    }
    __syncthreads();

    // ---- phase 2: argmax over this group's 128 codes, both columns ----
    float bestA = -CUDART_INF_F, bestB = -CUDART_INF_F;
    int biA = 0, biB = 0;
    {
        const float* cbase = s_w + g * CG * CDIM;
#pragma unroll 2
        for (int cc = 0; cc < CG; cc++) {
            const ulonglong2* r = (const ulonglong2*)(cbase + cc * CDIM);
            ulonglong2 c01 = r[0];   // warp-uniform LDS broadcast
            ulonglong2 c23 = r[1];
            u64 da = 0, db = 0;
            da = f2(c01.x, zeA[0], da);  db = f2(c01.x, zeB[0], db);
            da = f2(c01.y, zeA[1], da);  db = f2(c01.y, zeB[1], db);
            da = f2(c23.x, zeA[2], da);  db = f2(c23.x, zeB[2], db);
            da = f2(c23.y, zeA[3], da);  db = f2(c23.y, zeB[3], db);
            float la, ha, lb, hb;
            upk(la, ha, da);
            upk(lb, hb, db);
            float dotA = la + ha;
            float dotB = lb + hb;
            int c = g * CG + cc;
            if (dotA > bestA) { bestA = dotA; biA = c; }   // strict >: first max wins
            if (dotB > bestB) { bestB = dotB; biB = c; }
        }
    }
    s_best[g * TILE + slot * 2]     = bestA;
    s_best[g * TILE + slot * 2 + 1] = bestB;
    s_bi[g * TILE + slot * 2]       = biA;
    s_bi[g * TILE + slot * 2 + 1]   = biB;
    __syncthreads();

    // combine argmax across groups (ascending g keeps first-index semantics)
    int fbiA, fbiB;
    {
        float vA = s_best[slot * 2], vB = s_best[slot * 2 + 1];
        fbiA = s_bi[slot * 2];  fbiB = s_bi[slot * 2 + 1];
#pragma unroll
        for (int gg = 1; gg < NG; gg++) {
            float wA = s_best[gg * TILE + slot * 2];
            float wB = s_best[gg * TILE + slot * 2 + 1];
            if (wA > vA) { vA = wA; fbiA = s_bi[gg * TILE + slot * 2]; }
            if (wB > vB) { vB = wB; fbiB = s_bi[gg * TILE + slot * 2 + 1]; }
        }
    }
    if (g == 0)
        __stcs((float2*)(out + OFF_IDX + (size_t)b * TT + t0),
               make_float2((float)fbiA, (float)fbiB));

    // gather raw codebook rows (L1/L2 resident)
    const float4* cb4 = (const float4*)cb;
    float4 qa0 = __ldg(cb4 + 2 * fbiA);
    float4 qa1 = __ldg(cb4 + 2 * fbiA + 1);
    float4 qb0 = __ldg(cb4 + 2 * fbiB);
    float4 qb1 = __ldg(cb4 + 2 * fbiB + 1);

    // loss scalar (all 8 groups duplicate -> x0.125 at the end)
    float ls = 0.f;
    {
        float zqa[CDIM] = {qa0.x, qa0.y, qa0.z, qa0.w, qa1.x, qa1.y, qa1.z, qa1.w};
        float zqb[CDIM] = {qb0.x, qb0.y, qb0.z, qb0.w, qb1.x, qb1.y, qb1.z, qb1.w};
#pragma unroll
        for (int j = 0; j < 4; j++) {
            float a0, a1, b0, b1;
            upk(a0, a1, zeA[j]);
            upk(b0, b1, zeB[j]);
            float d0 = a0 - zqa[2 * j], d1 = a1 - zqa[2 * j + 1];
            float d2 = b0 - zqb[2 * j], d3 = b1 - zqb[2 * j + 1];
            ls = fmaf(d0, d0, ls);
            ls = fmaf(d1, d1, ls);
            ls = fmaf(d2, d2, ls);
            ls = fmaf(d3, d3, ls);
        }
    }

    // ---- stage out-proj weight + bias ----
    {
        const float4* src = (const float4*)g_wout;
        float4* dst = (float4*)s_w;
        for (int i = tid; i < DD * CDIM / 4; i += NTHREADS) dst[i] = src[i];
        for (int i = tid; i < DD; i += NTHREADS) s_bias[i] = __ldg(out_b + i);
    }
    __syncthreads();

    // ---- phase 3: out rows for this group's 128 d's, both columns ----
    {
        u64 zqA[4] = { pk(qa0.x, qa0.y), pk(qa0.z, qa0.w), pk(qa1.x, qa1.y), pk(qa1.z, qa1.w) };
        u64 zqB[4] = { pk(qb0.x, qb0.y), pk(qb0.z, qb0.w), pk(qb1.x, qb1.y), pk(qb1.z, qb1.w) };
        const ulonglong2* wp = (const ulonglong2*)(s_w + g * DG * CDIM);
        const float* bp = s_bias + g * DG;
        float* op = out + (size_t)b * (DD * TT) + (size_t)(g * DG) * TT + t0;
#pragma unroll 4
        for (int d = 0; d < DG; d++) {
            ulonglong2 w01 = wp[2 * d];        // warp-uniform LDS broadcast
            ulonglong2 w23 = wp[2 * d + 1];
            float bd = bp[d];
            u64 acA = 0, acB = 0;
            acA = f2(w01.x, zqA[0], acA);  acB = f2(w01.x, zqB[0], acB);
            acA = f2(w01.y, zqA[1], acA);  acB = f2(w01.y, zqB[1], acB);
            acA = f2(w23.x, zqA[2], acA);  acB = f2(w23.x, zqB[2], acB);
            acA = f2(w23.y, zqA[3], acA);  acB = f2(w23.y, zqB[3], acB);
            float la, ha, lb, hb;
            upk(la, ha, acA);
            upk(lb, hb, acB);
            __stcs((float2*)(op + (size_t)d * TT),
                   make_float2(la + ha + bd, lb + hb + bd));
        }
    }

    // ---- block loss reduction (deterministic) ----
#pragma unroll
    for (int m = 16; m > 0; m >>= 1)
        ls += __shfl_xor_sync(0xffffffffu, ls, m);
    if ((tid & 31) == 0) s_red[tid >> 5] = ls;
    __syncthreads();

    __shared__ bool s_amLast;
    if (tid == 0) {
        float tot = 0.f;
#pragma unroll
        for (int w = 0; w < NTHREADS / 32; w++) tot += s_red[w];
        g_losspart[blk] = tot * 0.125f;   // 8 groups quadruplicate each column
        __threadfence();
        unsigned int old = atomicAdd(&g_done, 1u);
        s_amLast = (old == GRID - 1);
    }
    __syncthreads();

    // last block performs the deterministic fixed-order final reduction
    if (s_amLast) {
        __threadfence();
        if (tid == 0) g_done = 0;          // self-reset for graph replay
        if (tid < BB) {
            const float* p = g_losspart + tid * TILES_PER_B;
            float s = 0.f;
            for (int i = 0; i < TILES_PER_B; i++) s += p[i];
            s *= (1.0f / (float)(CDIM * TT));
            out[OFF_CL + tid] = s;
            out[OFF_CB + tid] = s;
        }
    }
}

extern "C" void kernel_launch(void* const* d_in, const int* in_sizes, int n_in,
                              void* d_out, int out_size) {
    const float* z   = (const float*)d_in[0];
    const float* ipv = (const float*)d_in[1];
    const float* ipg = (const float*)d_in[2];
    const float* ipb = (const float*)d_in[3];
    const float* opv = (const float*)d_in[4];
    const float* opg = (const float*)d_in[5];
    const float* opb = (const float*)d_in[6];
    const float* cb  = (const float*)d_in[7];
    float* out = (float*)d_out;

    const int smem_bytes = 32768 + 16384 + 4096 + 64;  // s_w + exchange + bias + red
    cudaFuncSetAttribute(vq_main, cudaFuncAttributeMaxDynamicSharedMemorySize, smem_bytes);

    vq_prep<<<CDIM + 4, 256>>>(ipv, ipg, opv, opg, cb);
    vq_main<<<GRID, NTHREADS, smem_bytes>>>(z, ipb, opb, cb, out);
}

// round 8
// speedup vs baseline: 1.3442x; 1.0175x over previous
#include <cuda_runtime.h>
#include <math_constants.h>

// Problem constants
#define BB   16
#define DD   1024
#define TT   4096
#define CDIM 8
#define CSZ  1024

#define NTHREADS 512
#define NG   4                     // groups = 4 warps each (warp-uniform)
#define SLOTS 128                  // thread slots per group
#define TV   2                     // t-columns per thread
#define TILE (SLOTS * TV)          // 256 t per block
#define DG   (DD / NG)             // 256 d per group
#define CG   (CSZ / NG)            // 256 codes per group
#define TILES_PER_B (TT / TILE)    // 16
#define GRID (BB * TILES_PER_B)    // 256 (single wave at occ 2)

// Output layout (concatenated float32):
// out [B,D,T], commitment_loss [B], codebook_loss [B], indices [B,T], z_e [B,CD,T]
#define OFF_CL  (BB * DD * TT)
#define OFF_CB  (OFF_CL + BB)
#define OFF_IDX (OFF_CB + BB)
#define OFF_ZE  (OFF_IDX + BB * TT)

// Device-global scratch
__device__ float g_winT[DD * CDIM];   // in-proj weight transposed [d][k]
__device__ float g_wout[DD * CDIM];   // out-proj weight [d][k]
__device__ float g_cbn[CSZ * CDIM];   // normalized codebook [c][k]
__device__ float g_losspart[GRID];
__device__ unsigned int g_done;       // zero-init; self-resetting

// ---------------- f32x2 packed helpers ----------------
typedef unsigned long long u64;

__device__ __forceinline__ u64 pk(float lo, float hi) {
    u64 r; asm("mov.b64 %0, {%1, %2};" : "=l"(r) : "f"(lo), "f"(hi)); return r;
}
__device__ __forceinline__ void upk(float& lo, float& hi, u64 v) {
    asm("mov.b64 {%0, %1}, %2;" : "=f"(lo), "=f"(hi) : "l"(v));
}
__device__ __forceinline__ u64 f2(u64 a, u64 b, u64 c) {
    u64 d; asm("fma.rn.f32x2 %0, %1, %2, %3;" : "=l"(d) : "l"(a), "l"(b), "l"(c)); return d;
}
__device__ __forceinline__ u64 a2(u64 a, u64 b) {
    u64 d; asm("add.rn.f32x2 %0, %1, %2;" : "=l"(d) : "l"(a), "l"(b)); return d;
}

// ---------------------------------------------------------------------------
// Prep: blocks 0..7 -> weight-norm in_proj row o (norm over D), transpose.
//       blocks 8..11 -> weight-norm out_proj rows + l2-normalized codebook.
// ---------------------------------------------------------------------------
__global__ void vq_prep(const float* __restrict__ ipv, const float* __restrict__ ipg,
                        const float* __restrict__ opv, const float* __restrict__ opg,
                        const float* __restrict__ cb) {
    if (blockIdx.x < CDIM) {
        int o = blockIdx.x;
        __shared__ float red[256];
        float s = 0.f;
        for (int d = threadIdx.x; d < DD; d += blockDim.x) {
            float x = ipv[o * DD + d];
            s = fmaf(x, x, s);
        }
        red[threadIdx.x] = s;
        __syncthreads();
        for (int off = 128; off > 0; off >>= 1) {
            if (threadIdx.x < off) red[threadIdx.x] += red[threadIdx.x + off];
            __syncthreads();
        }
        float scale = ipg[o] / sqrtf(red[0]);
        for (int d = threadIdx.x; d < DD; d += blockDim.x)
            g_winT[d * CDIM + o] = ipv[o * DD + d] * scale;
    } else {
        int i = (blockIdx.x - CDIM) * 256 + threadIdx.x;
        if (i < DD) {
            float vv[CDIM];
            float s = 0.f;
#pragma unroll
            for (int c = 0; c < CDIM; c++) { vv[c] = opv[i * CDIM + c]; s = fmaf(vv[c], vv[c], s); }
            float sc = opg[i] / sqrtf(s);
#pragma unroll
            for (int c = 0; c < CDIM; c++) g_wout[i * CDIM + c] = vv[c] * sc;
        }
        if (i < CSZ) {
            float vv[CDIM];
            float s = 0.f;
#pragma unroll
            for (int k = 0; k < CDIM; k++) { vv[k] = cb[i * CDIM + k]; s = fmaf(vv[k], vv[k], s); }
            float inv = 1.f / fmaxf(sqrtf(s), 1e-12f);
#pragma unroll
            for (int k = 0; k < CDIM; k++) g_cbn[i * CDIM + k] = vv[k] * inv;
        }
    }
}

// Dynamic smem layout (bytes):
//   s_winT [0,      32768)
//   s_cbn  [32768,  65536)
//   s_wout [65536,  98304)
//   s_ex   [98304, 114688)  16 KB: 2-round partial exchange; later aliased:
//            [+0, +4K)  s_best [NG][TILE] floats
//            [+4K,+8K)  s_bi   [NG][TILE] ints
//            [+8K,+12K) s_bias [DD] floats
//   s_red  [114688, 114752)
// Total 114752 B/block -> 2 blocks/SM (224.1 KB of 228).
// ---------------------------------------------------------------------------
__global__ void __launch_bounds__(NTHREADS, 2)
vq_main(const float* __restrict__ z,
        const float* __restrict__ in_b,
        const float* __restrict__ out_b,
        const float* __restrict__ cb,
        float* __restrict__ out) {
    extern __shared__ __align__(16) char smem[];
    float* s_winT = (float*)smem;
    float* s_cbn  = (float*)(smem + 32768);
    float* s_wout = (float*)(smem + 65536);
    u64*   s_ex   = (u64*)(smem + 98304);
    float* s_best = (float*)(smem + 98304);
    int*   s_bi   = (int*)(smem + 98304 + 4096);
    float* s_bias = (float*)(smem + 98304 + 8192);
    float* s_red  = (float*)(smem + 114688);

    const int tid  = threadIdx.x;
    const int g    = tid >> 7;          // group 0..3 (uniform across its 4 warps)
    const int slot = tid & (SLOTS - 1); // 0..127
    const int blk  = blockIdx.x;
    const int b    = blk / TILES_PER_B;
    const int t0   = (blk % TILES_PER_B) * TILE + slot * TV;

    // ---- stage ALL tables once (96 KB) ----
    {
        const float4* w1 = (const float4*)g_winT;
        const float4* w2 = (const float4*)g_cbn;
        const float4* w3 = (const float4*)g_wout;
        float4* d1 = (float4*)s_winT;
        float4* d2 = (float4*)s_cbn;
        float4* d3 = (float4*)s_wout;
        for (int i = tid; i < DD * CDIM / 4; i += NTHREADS) {
            d1[i] = w1[i];
            d2[i] = w2[i];
            d3[i] = w3[i];
        }
    }
    __syncthreads();

    // ---- phase 1: partial z_e over this group's 256 d's, 2 columns ----
    u64 aA[4] = {0, 0, 0, 0};
    u64 aB[4] = {0, 0, 0, 0};
    {
        const float* zp = z + (size_t)b * (DD * TT) + (size_t)(g * DG) * TT + t0;
        const ulonglong2* wp = (const ulonglong2*)(s_winT + g * DG * CDIM);
#pragma unroll 4
        for (int d = 0; d < DG; d++) {
            float2 zv = __ldcs((const float2*)(zp + (size_t)d * TT));
            ulonglong2 w01 = wp[2 * d];        // warp-uniform LDS broadcast
            ulonglong2 w23 = wp[2 * d + 1];
            u64 za = pk(zv.x, zv.x);
            u64 zb = pk(zv.y, zv.y);
            aA[0] = f2(w01.x, za, aA[0]);  aB[0] = f2(w01.x, zb, aB[0]);
            aA[1] = f2(w01.y, za, aA[1]);  aB[1] = f2(w01.y, zb, aB[1]);
            aA[2] = f2(w23.x, za, aA[2]);  aB[2] = f2(w23.x, zb, aB[2]);
            aA[3] = f2(w23.y, za, aA[3]);  aB[3] = f2(w23.y, zb, aB[3]);
        }
    }

    // ---- 2-round partial exchange (16 KB buffer), combine ascending g ----
    u64 zeA[4], zeB[4];
    const float2* bb = (const float2*)in_b;
#pragma unroll
    for (int r = 0; r < 2; r++) {
        // publish j = 2r, 2r+1
#pragma unroll
        for (int jj = 0; jj < 2; jj++) {
            s_ex[((jj * 2 + 0) * NG + g) * SLOTS + slot] = aA[2 * r + jj];
            s_ex[((jj * 2 + 1) * NG + g) * SLOTS + slot] = aB[2 * r + jj];
        }
        __syncthreads();
#pragma unroll
        for (int jj = 0; jj < 2; jj++) {
            int j = 2 * r + jj;
            float2 bj = __ldg(bb + j);
            u64 bp = pk(bj.x, bj.y);
            u64 sa = s_ex[((jj * 2 + 0) * NG + 0) * SLOTS + slot];
            u64 sb = s_ex[((jj * 2 + 1) * NG + 0) * SLOTS + slot];
#pragma unroll
            for (int gg = 1; gg < NG; gg++) {
                sa = a2(sa, s_ex[((jj * 2 + 0) * NG + gg) * SLOTS + slot]);
                sb = a2(sb, s_ex[((jj * 2 + 1) * NG + gg) * SLOTS + slot]);
            }
            zeA[j] = a2(sa, bp);
            zeB[j] = a2(sb, bp);
        }
        __syncthreads();   // reads complete before buffer reuse
    }

    // stage out-proj bias into freed exchange space (consumed in P3, ordered
    // by the pre-P3 argmax sync); also write z_e (group 0 only)
    for (int i = tid; i < DD; i += NTHREADS) s_bias[i] = __ldg(out_b + i);
    if (g == 0) {
        float* zeo = out + OFF_ZE + (size_t)b * (CDIM * TT) + t0;
#pragma unroll
        for (int j = 0; j < 4; j++) {
            float a0, a1, b0, b1;
            upk(a0, a1, zeA[j]);
            upk(b0, b1, zeB[j]);
            __stcs((float2*)(zeo + (size_t)(2 * j) * TT),     make_float2(a0, b0));
            __stcs((float2*)(zeo + (size_t)(2 * j + 1) * TT), make_float2(a1, b1));
        }
    }

    // ---- phase 2: argmax over this group's 256 codes, both columns ----
    float bestA = -CUDART_INF_F, bestB = -CUDART_INF_F;
    int biA = 0, biB = 0;
    {
        const float* cbase = s_cbn + g * CG * CDIM;
#pragma unroll 2
        for (int cc = 0; cc < CG; cc++) {
            const ulonglong2* r = (const ulonglong2*)(cbase + cc * CDIM);
            ulonglong2 c01 = r[0];   // warp-uniform LDS broadcast
            ulonglong2 c23 = r[1];
            u64 da = 0, db = 0;
            da = f2(c01.x, zeA[0], da);  db = f2(c01.x, zeB[0], db);
            da = f2(c01.y, zeA[1], da);  db = f2(c01.y, zeB[1], db);
            da = f2(c23.x, zeA[2], da);  db = f2(c23.x, zeB[2], db);
            da = f2(c23.y, zeA[3], da);  db = f2(c23.y, zeB[3], db);
            float la, ha, lb, hb;
            upk(la, ha, da);
            upk(lb, hb, db);
            float dotA = la + ha;
            float dotB = lb + hb;
            int c = g * CG + cc;
            if (dotA > bestA) { bestA = dotA; biA = c; }   // strict >: first max wins
            if (dotB > bestB) { bestB = dotB; biB = c; }
        }
    }
    s_best[g * TILE + slot * 2]     = bestA;
    s_best[g * TILE + slot * 2 + 1] = bestB;
    s_bi[g * TILE + slot * 2]       = biA;
    s_bi[g * TILE + slot * 2 + 1]   = biB;
    __syncthreads();

    // combine argmax across groups (ascending g keeps first-index semantics)
    int fbiA, fbiB;
    {
        float vA = s_best[slot * 2], vB = s_best[slot * 2 + 1];
        fbiA = s_bi[slot * 2];  fbiB = s_bi[slot * 2 + 1];
#pragma unroll
        for (int gg = 1; gg < NG; gg++) {
            float wA = s_best[gg * TILE + slot * 2];
            float wB = s_best[gg * TILE + slot * 2 + 1];
            if (wA > vA) { vA = wA; fbiA = s_bi[gg * TILE + slot * 2]; }
            if (wB > vB) { vB = wB; fbiB = s_bi[gg * TILE + slot * 2 + 1]; }
        }
    }
    if (g == 0)
        __stcs((float2*)(out + OFF_IDX + (size_t)b * TT + t0),
               make_float2((float)fbiA, (float)fbiB));

    // gather raw codebook rows (L1/L2 resident)
    const float4* cb4 = (const float4*)cb;
    float4 qa0 = __ldg(cb4 + 2 * fbiA);
    float4 qa1 = __ldg(cb4 + 2 * fbiA + 1);
    float4 qb0 = __ldg(cb4 + 2 * fbiB);
    float4 qb1 = __ldg(cb4 + 2 * fbiB + 1);

    // loss scalar (all 4 groups duplicate -> x0.25 at the end)
    float ls = 0.f;
    {
        float zqa[CDIM] = {qa0.x, qa0.y, qa0.z, qa0.w, qa1.x, qa1.y, qa1.z, qa1.w};
        float zqb[CDIM] = {qb0.x, qb0.y, qb0.z, qb0.w, qb1.x, qb1.y, qb1.z, qb1.w};
#pragma unroll
        for (int j = 0; j < 4; j++) {
            float a0, a1, b0, b1;
            upk(a0, a1, zeA[j]);
            upk(b0, b1, zeB[j]);
            float d0 = a0 - zqa[2 * j], d1 = a1 - zqa[2 * j + 1];
            float d2 = b0 - zqb[2 * j], d3 = b1 - zqb[2 * j + 1];
            ls = fmaf(d0, d0, ls);
            ls = fmaf(d1, d1, ls);
            ls = fmaf(d2, d2, ls);
            ls = fmaf(d3, d3, ls);
        }
    }

    // ---- phase 3 (NO sync: wout resident, bias already staged) ----
    {
        u64 zqA[4] = { pk(qa0.x, qa0.y), pk(qa0.z, qa0.w), pk(qa1.x, qa1.y), pk(qa1.z, qa1.w) };
        u64 zqB[4] = { pk(qb0.x, qb0.y), pk(qb0.z, qb0.w), pk(qb1.x, qb1.y), pk(qb1.z, qb1.w) };
        const ulonglong2* wp = (const ulonglong2*)(s_wout + g * DG * CDIM);
        const float* bp = s_bias + g * DG;
        float* op = out + (size_t)b * (DD * TT) + (size_t)(g * DG) * TT + t0;
#pragma unroll 4
        for (int d = 0; d < DG; d++) {
            ulonglong2 w01 = wp[2 * d];        // warp-uniform LDS broadcast
            ulonglong2 w23 = wp[2 * d + 1];
            float bd = bp[d];
            u64 acA = 0, acB = 0;
            acA = f2(w01.x, zqA[0], acA);  acB = f2(w01.x, zqB[0], acB);
            acA = f2(w01.y, zqA[1], acA);  acB = f2(w01.y, zqB[1], acB);
            acA = f2(w23.x, zqA[2], acA);  acB = f2(w23.x, zqB[2], acB);
            acA = f2(w23.y, zqA[3], acA);  acB = f2(w23.y, zqB[3], acB);
            float la, ha, lb, hb;
            upk(la, ha, acA);
            upk(lb, hb, acB);
            __stcs((float2*)(op + (size_t)d * TT),
                   make_float2(la + ha + bd, lb + hb + bd));
        }
    }

    // ---- block loss reduction (deterministic) ----
#pragma unroll
    for (int m = 16; m > 0; m >>= 1)
        ls += __shfl_xor_sync(0xffffffffu, ls, m);
    if ((tid & 31) == 0) s_red[tid >> 5] = ls;
    __syncthreads();

    __shared__ bool s_amLast;
    if (tid == 0) {
        float tot = 0.f;
#pragma unroll
        for (int w = 0; w < NTHREADS / 32; w++) tot += s_red[w];
        g_losspart[blk] = tot * 0.25f;   // 4 groups quadruplicate each column
        __threadfence();
        unsigned int old = atomicAdd(&g_done, 1u);
        s_amLast = (old == GRID - 1);
    }
    __syncthreads();

    // last block: deterministic fixed-order final reduction
    if (s_amLast) {
        __threadfence();
        if (tid == 0) g_done = 0;          // self-reset for graph replay
        if (tid < BB) {
            const float* p = g_losspart + tid * TILES_PER_B;
            float s = 0.f;
            for (int i = 0; i < TILES_PER_B; i++) s += p[i];
            s *= (1.0f / (float)(CDIM * TT));
            out[OFF_CL + tid] = s;
            out[OFF_CB + tid] = s;
        }
    }
}

extern "C" void kernel_launch(void* const* d_in, const int* in_sizes, int n_in,
                              void* d_out, int out_size) {
    const float* z   = (const float*)d_in[0];
    const float* ipv = (const float*)d_in[1];
    const float* ipg = (const float*)d_in[2];
    const float* ipb = (const float*)d_in[3];
    const float* opv = (const float*)d_in[4];
    const float* opg = (const float*)d_in[5];
    const float* opb = (const float*)d_in[6];
    const float* cb  = (const float*)d_in[7];
    float* out = (float*)d_out;

    const int smem_bytes = 114752;   // 3 tables + 16K exchange + red
    cudaFuncSetAttribute(vq_main, cudaFuncAttributeMaxDynamicSharedMemorySize, smem_bytes);

    vq_prep<<<CDIM + 4, 256>>>(ipv, ipg, opv, opg, cb);
    vq_main<<<GRID, NTHREADS, smem_bytes>>>(z, ipb, opb, cb, out);
}